// round 5
// baseline (speedup 1.0000x reference)
#include <cuda_runtime.h>
#include <math.h>

// GRU: B=128, T=512, I=256, H=512. out = final h [1,128,512] fp32.
// Persistent kernel, 128 CTAs (4 batch-chunks x 32 j-slices), weights in SMEM.
// 512 threads/CTA. Thread tile: 2j x 2b x 3 gates, K split 4-way across lanes.
// Split grid barrier overlapped with the x-chunk compute of the next step.

#define BATCH 128
#define TT    512
#define II    256
#define HH    512
#define GB    4
#define GJ    32
#define BC    32
#define JC    16
#define NCTA  (GB*GJ)
#define NTHR  512
#define USTRIDE 260          // stride % 32 banks == 4 -> exact 4-phase U loads
#define WSTRIDE 772

#define SMEM_W   (48*WSTRIDE)
#define SMEM_U   (32*USTRIDE)
#define SMEM_FLOATS (SMEM_W + 2*SMEM_U + 64)
#define SMEM_BYTES  (SMEM_FLOATS*4)

typedef unsigned long long ull;

__device__ float g_h[2][BATCH*HH];
__device__ unsigned int g_count = 0;
__device__ unsigned int g_phase = 0;

__device__ __forceinline__ void fma2(ull &d, ull a, ull b) {
    asm("fma.rn.f32x2 %0, %1, %2, %0;" : "+l"(d) : "l"(a), "l"(b));
}
__device__ __forceinline__ float foldadd(ull v) {
    float lo, hi;
    asm("mov.b64 {%0, %1}, %2;" : "=f"(lo), "=f"(hi) : "l"(v));
    return lo + hi;
}
__device__ __forceinline__ float red4(float v) {
    v += __shfl_xor_sync(0xFFFFFFFFu, v, 1);
    v += __shfl_xor_sync(0xFFFFFFFFu, v, 2);
    return v;
}
__device__ __forceinline__ float sigm(float x) {
    return 1.0f / (1.0f + __expf(-x));
}

__device__ __forceinline__ void grid_sync_full() {
    __syncthreads();
    if (threadIdx.x == 0) {
        __threadfence();
        unsigned gen = *((volatile unsigned*)&g_phase);
        if (atomicAdd(&g_count, 1u) == NCTA - 1u) {
            g_count = 0;
            __threadfence();
            *((volatile unsigned*)&g_phase) = gen + 1u;
        } else {
            while (*((volatile unsigned*)&g_phase) == gen) { __nanosleep(32); }
        }
        __threadfence();
    }
    __syncthreads();
}

extern "C" __global__ void __launch_bounds__(NTHR, 1)
gru_persistent_kernel(const float* __restrict__ x,      // [B, T, I]
                      const float* __restrict__ W_ih,   // [3H, I]
                      const float* __restrict__ W_hh,   // [3H, H]
                      const float* __restrict__ b_ih,   // [3H]
                      const float* __restrict__ b_hh,   // [3H]
                      float* __restrict__ out)          // [1, B, H]
{
    extern __shared__ float smem[];
    float* W_s  = smem;                 // [48][WSTRIDE] fused [W_ih | W_hh]
    float* U_s0 = W_s + SMEM_W;         // [32][USTRIDE]  (x chunk / h[256:512])
    float* U_s1 = U_s0 + SMEM_U;        // [32][USTRIDE]  (h[0:256])
    float* B_s  = U_s1 + SMEM_U;        // [64]

    const int tid = threadIdx.x;
    const int bx  = blockIdx.x;
    const int gb  = bx & (GB - 1);
    const int gj  = bx >> 2;
    const int b0  = gb * BC;
    const int j0  = gj * JC;

    // ---- one-time: weight tile into SMEM (rows 0-15 r, 16-31 z, 32-47 n) ----
    for (int idx = tid; idx < 48 * 768; idx += NTHR) {
        int row = idx / 768;
        int col = idx - row * 768;
        int G;
        if (row < 16)      G = j0 + row;
        else if (row < 32) G = 512 + j0 + (row - 16);
        else               G = 1024 + j0 + (row - 32);
        float v = (col < II) ? W_ih[G * II + col] : W_hh[G * HH + (col - II)];
        W_s[row * WSTRIDE + col] = v;
    }
    if (tid < 64) {
        int i = tid & 15;
        float v;
        if (tid < 16)      v = b_ih[j0 + i]       + b_hh[j0 + i];        // r
        else if (tid < 32) v = b_ih[512 + j0 + i] + b_hh[512 + j0 + i];  // z
        else if (tid < 48) v = b_ih[1024 + j0 + i];                      // xn
        else               v = b_hh[1024 + j0 + i];                      // hn
        B_s[tid] = v;
    }

    // zero h0, stage x(t=0) into buf0
    for (int idx = bx * NTHR + tid; idx < BATCH * HH; idx += NCTA * NTHR)
        g_h[0][idx] = 0.0f;

    const int ldrow = tid >> 4;          // 0..31
    const int ldv   = tid & 15;          // 0..15
    {
        const float4* xsrc = (const float4*)(x + ((size_t)(b0 + ldrow) * TT) * II);
        float4* dx = (float4*)(U_s0 + ldrow * USTRIDE);
        #pragma unroll
        for (int it = 0; it < 4; it++)
            dx[ldv + 16 * it] = xsrc[ldv + 16 * it];
    }

    grid_sync_full();   // phase -> 1; h0 + x(0) visible

    // thread mapping
    const int s     = tid & 3;           // k-slice lane
    const int bslot = (tid >> 2) & 15;   // batch slots: rows bslot, bslot+16
    const int jp    = tid >> 6;          // 0..7 -> j pair

    const float br_[2]  = { B_s[2*jp],      B_s[2*jp + 1] };
    const float bz_[2]  = { B_s[16 + 2*jp], B_s[16 + 2*jp + 1] };
    const float bxn_[2] = { B_s[32 + 2*jp], B_s[32 + 2*jp + 1] };
    const float bhn_[2] = { B_s[48 + 2*jp], B_s[48 + 2*jp + 1] };

    // W row pointers (ulonglong2 units), k-slice s baked in
    const ulonglong2* wR[2], * wZ[2], * wN[2];
    wR[0] = (const ulonglong2*)(W_s + (2*jp+0)*WSTRIDE) + s;
    wR[1] = (const ulonglong2*)(W_s + (2*jp+1)*WSTRIDE) + s;
    wZ[0] = (const ulonglong2*)(W_s + (16+2*jp+0)*WSTRIDE) + s;
    wZ[1] = (const ulonglong2*)(W_s + (16+2*jp+1)*WSTRIDE) + s;
    wN[0] = (const ulonglong2*)(W_s + (32+2*jp+0)*WSTRIDE) + s;
    wN[1] = (const ulonglong2*)(W_s + (32+2*jp+1)*WSTRIDE) + s;

    const ulonglong2* u0base0 = (const ulonglong2*)(U_s0 + bslot*USTRIDE) + s;
    const ulonglong2* u1base0 = (const ulonglong2*)(U_s0 + (bslot+16)*USTRIDE) + s;
    const ulonglong2* u0base1 = (const ulonglong2*)(U_s1 + bslot*USTRIDE) + s;
    const ulonglong2* u1base1 = (const ulonglong2*)(U_s1 + (bslot+16)*USTRIDE) + s;

    for (int t = 0; t < TT; t++) {
        const int rp = t & 1;
        const int wp = rp ^ 1;

        ull ar[2][2], az[2][2], an[2][2];
        float xn[2][2];
        #pragma unroll
        for (int jj = 0; jj < 2; jj++)
            #pragma unroll
            for (int q = 0; q < 2; q++) { ar[jj][q] = 0; az[jj][q] = 0; an[jj][q] = 0; }

        // ---- chunk 0: x gates from buf0 (no dependence on peers' h) ----
        {
            const ulonglong2* pR0 = wR[0], * pR1 = wR[1];
            const ulonglong2* pZ0 = wZ[0], * pZ1 = wZ[1];
            const ulonglong2* pN0 = wN[0], * pN1 = wN[1];
            const ulonglong2* pu0 = u0base0, * pu1 = u1base0;
            #pragma unroll 4
            for (int i = 0; i < 16; i++) {
                ulonglong2 r0 = pR0[4*i], r1 = pR1[4*i];
                ulonglong2 z0 = pZ0[4*i], z1 = pZ1[4*i];
                ulonglong2 n0 = pN0[4*i], n1 = pN1[4*i];
                ulonglong2 ua = pu0[4*i], ub = pu1[4*i];
                fma2(ar[0][0], r0.x, ua.x); fma2(ar[0][0], r0.y, ua.y);
                fma2(ar[0][1], r0.x, ub.x); fma2(ar[0][1], r0.y, ub.y);
                fma2(ar[1][0], r1.x, ua.x); fma2(ar[1][0], r1.y, ua.y);
                fma2(ar[1][1], r1.x, ub.x); fma2(ar[1][1], r1.y, ub.y);
                fma2(az[0][0], z0.x, ua.x); fma2(az[0][0], z0.y, ua.y);
                fma2(az[0][1], z0.x, ub.x); fma2(az[0][1], z0.y, ub.y);
                fma2(az[1][0], z1.x, ua.x); fma2(az[1][0], z1.y, ua.y);
                fma2(az[1][1], z1.x, ub.x); fma2(az[1][1], z1.y, ub.y);
                fma2(an[0][0], n0.x, ua.x); fma2(an[0][0], n0.y, ua.y);
                fma2(an[0][1], n0.x, ub.x); fma2(an[0][1], n0.y, ub.y);
                fma2(an[1][0], n1.x, ua.x); fma2(an[1][0], n1.y, ua.y);
                fma2(an[1][1], n1.x, ub.x); fma2(an[1][1], n1.y, ub.y);
            }
        }
        #pragma unroll
        for (int jj = 0; jj < 2; jj++)
            #pragma unroll
            for (int q = 0; q < 2; q++) { xn[jj][q] = foldadd(an[jj][q]); an[jj][q] = 0; }

        // ---- wait for peers' h(t-1) (overlapped by chunk-0 compute above) ----
        if (tid == 0) {
            while (*((volatile unsigned*)&g_phase) < (unsigned)(t + 1)) { __nanosleep(32); }
            __threadfence();
        }
        __syncthreads();

        // ---- stage h: h[0:256] -> buf1, h[256:512] -> buf0 ----
        {
            const float4* hsrc = (const float4*)(g_h[rp] + (b0 + ldrow) * HH);
            float4* d1 = (float4*)(U_s1 + ldrow * USTRIDE);
            float4* d0 = (float4*)(U_s0 + ldrow * USTRIDE);
            #pragma unroll
            for (int it = 0; it < 4; it++) d1[ldv + 16*it] = hsrc[ldv + 16*it];
            #pragma unroll
            for (int it = 0; it < 4; it++) d0[ldv + 16*it] = hsrc[64 + ldv + 16*it];
        }
        __syncthreads();

        // ---- chunks 1 (buf1) and 2 (buf0): h gates ----
        #pragma unroll
        for (int c = 1; c < 3; c++) {
            const ulonglong2* pR0 = wR[0] + c*64, * pR1 = wR[1] + c*64;
            const ulonglong2* pZ0 = wZ[0] + c*64, * pZ1 = wZ[1] + c*64;
            const ulonglong2* pN0 = wN[0] + c*64, * pN1 = wN[1] + c*64;
            const ulonglong2* pu0 = (c == 1) ? u0base1 : u0base0;
            const ulonglong2* pu1 = (c == 1) ? u1base1 : u1base0;
            #pragma unroll 4
            for (int i = 0; i < 16; i++) {
                ulonglong2 r0 = pR0[4*i], r1 = pR1[4*i];
                ulonglong2 z0 = pZ0[4*i], z1 = pZ1[4*i];
                ulonglong2 n0 = pN0[4*i], n1 = pN1[4*i];
                ulonglong2 ua = pu0[4*i], ub = pu1[4*i];
                fma2(ar[0][0], r0.x, ua.x); fma2(ar[0][0], r0.y, ua.y);
                fma2(ar[0][1], r0.x, ub.x); fma2(ar[0][1], r0.y, ub.y);
                fma2(ar[1][0], r1.x, ua.x); fma2(ar[1][0], r1.y, ua.y);
                fma2(ar[1][1], r1.x, ub.x); fma2(ar[1][1], r1.y, ub.y);
                fma2(az[0][0], z0.x, ua.x); fma2(az[0][0], z0.y, ua.y);
                fma2(az[0][1], z0.x, ub.x); fma2(az[0][1], z0.y, ub.y);
                fma2(az[1][0], z1.x, ua.x); fma2(az[1][0], z1.y, ua.y);
                fma2(az[1][1], z1.x, ub.x); fma2(az[1][1], z1.y, ub.y);
                fma2(an[0][0], n0.x, ua.x); fma2(an[0][0], n0.y, ua.y);
                fma2(an[0][1], n0.x, ub.x); fma2(an[0][1], n0.y, ub.y);
                fma2(an[1][0], n1.x, ua.x); fma2(an[1][0], n1.y, ua.y);
                fma2(an[1][1], n1.x, ub.x); fma2(an[1][1], n1.y, ub.y);
            }
        }

        // ---- reduce + gates + h update ----
        float vr[2][2], vz[2][2], vh[2][2];
        #pragma unroll
        for (int jj = 0; jj < 2; jj++)
            #pragma unroll
            for (int q = 0; q < 2; q++) {
                vr[jj][q] = red4(foldadd(ar[jj][q]));
                vz[jj][q] = red4(foldadd(az[jj][q]));
                vh[jj][q] = red4(foldadd(an[jj][q]));
                xn[jj][q] = red4(xn[jj][q]);
            }

        if (s == 0) {
            #pragma unroll
            for (int q = 0; q < 2; q++) {
                const int b_local = bslot + 16 * q;
                const int bg = b0 + b_local;
                float2 hnew;
                #pragma unroll
                for (int jj = 0; jj < 2; jj++) {
                    const int j = j0 + 2 * jp + jj;
                    float r = sigm(vr[jj][q] + br_[jj]);
                    float z = sigm(vz[jj][q] + bz_[jj]);
                    float n = tanhf(xn[jj][q] + bxn_[jj] + r * (vh[jj][q] + bhn_[jj]));
                    const float* hbuf = (j < 256) ? U_s1 : U_s0;
                    float hold = hbuf[b_local * USTRIDE + (j & 255)];
                    float hv = n + z * (hold - n);
                    if (jj == 0) hnew.x = hv; else hnew.y = hv;
                }
                *(float2*)(g_h[wp] + bg * HH + j0 + 2 * jp) = hnew;
                if (t == TT - 1)
                    *(float2*)(out + bg * HH + j0 + 2 * jp) = hnew;
            }
        }

        __syncthreads();   // all h writes + all buf0/buf1 reads done

        // ---- arrive (peers may proceed once all CTAs reach here) ----
        if (tid == 0) {
            __threadfence();
            if (atomicAdd(&g_count, 1u) == NCTA - 1u) {
                g_count = 0;
                __threadfence();
                *((volatile unsigned*)&g_phase) = (unsigned)(t + 2);
            }
        }

        // ---- stage x(t+1) into buf0 (independent of peers) ----
        if (t < TT - 1) {
            const float4* xsrc = (const float4*)(x + ((size_t)(b0 + ldrow) * TT + (t + 1)) * II);
            float4* dx = (float4*)(U_s0 + ldrow * USTRIDE);
            #pragma unroll
            for (int it = 0; it < 4; it++)
                dx[ldv + 16 * it] = xsrc[ldv + 16 * it];
        }
        __syncthreads();
    }
}

extern "C" void kernel_launch(void* const* d_in, const int* in_sizes, int n_in,
                              void* d_out, int out_size) {
    (void)in_sizes; (void)n_in; (void)out_size;
    cudaFuncSetAttribute(gru_persistent_kernel,
                         cudaFuncAttributeMaxDynamicSharedMemorySize, SMEM_BYTES);
    gru_persistent_kernel<<<NCTA, NTHR, SMEM_BYTES>>>(
        (const float*)d_in[0],
        (const float*)d_in[1],
        (const float*)d_in[2],
        (const float*)d_in[3],
        (const float*)d_in[4],
        (float*)d_out);
}

// round 6
// speedup vs baseline: 1.0012x; 1.0012x over previous
#include <cuda_runtime.h>
#include <math.h>

// GRU: B=128, T=512, I=256, H=512. out = final h [1,128,512] fp32.
// Persistent kernel, 128 CTAs (4 batch-chunks x 32 j-slices), weights in SMEM.
// 512 threads/CTA. Thread tile: 2j x 2b x 3 gates, K split 4-way across lanes.
// Split grid barrier overlapped with the x-chunk compute of the next step.

#define BATCH 128
#define TT    512
#define II    256
#define HH    512
#define GB    4
#define GJ    32
#define BC    32
#define JC    16
#define NCTA  (GB*GJ)
#define NTHR  512
#define USTRIDE 260          // stride % 32 banks == 4 -> exact 4-phase U loads
#define WSTRIDE 772

#define SMEM_W   (48*WSTRIDE)
#define SMEM_U   (32*USTRIDE)
#define SMEM_FLOATS (SMEM_W + 2*SMEM_U + 64)
#define SMEM_BYTES  (SMEM_FLOATS*4)

typedef unsigned long long ull;

__device__ float g_h[2][BATCH*HH];
__device__ unsigned int g_count = 0;
__device__ unsigned int g_phase = 0;

__device__ __forceinline__ void fma2(ull &d, ull a, ull b) {
    asm("fma.rn.f32x2 %0, %1, %2, %0;" : "+l"(d) : "l"(a), "l"(b));
}
__device__ __forceinline__ float foldadd(ull v) {
    float lo, hi;
    asm("mov.b64 {%0, %1}, %2;" : "=f"(lo), "=f"(hi) : "l"(v));
    return lo + hi;
}
__device__ __forceinline__ float red4(float v) {
    v += __shfl_xor_sync(0xFFFFFFFFu, v, 1);
    v += __shfl_xor_sync(0xFFFFFFFFu, v, 2);
    return v;
}
__device__ __forceinline__ float sigm(float x) {
    return 1.0f / (1.0f + __expf(-x));
}

__device__ __forceinline__ void grid_sync_full() {
    __syncthreads();
    if (threadIdx.x == 0) {
        __threadfence();
        unsigned gen = *((volatile unsigned*)&g_phase);
        if (atomicAdd(&g_count, 1u) == NCTA - 1u) {
            g_count = 0;
            __threadfence();
            *((volatile unsigned*)&g_phase) = gen + 1u;
        } else {
            while (*((volatile unsigned*)&g_phase) == gen) { __nanosleep(32); }
        }
        __threadfence();
    }
    __syncthreads();
}

extern "C" __global__ void __launch_bounds__(NTHR, 1)
gru_persistent_kernel(const float* __restrict__ x,      // [B, T, I]
                      const float* __restrict__ W_ih,   // [3H, I]
                      const float* __restrict__ W_hh,   // [3H, H]
                      const float* __restrict__ b_ih,   // [3H]
                      const float* __restrict__ b_hh,   // [3H]
                      float* __restrict__ out)          // [1, B, H]
{
    extern __shared__ float smem[];
    float* W_s  = smem;                 // [48][WSTRIDE] fused [W_ih | W_hh]
    float* U_s0 = W_s + SMEM_W;         // [32][USTRIDE]  (x chunk / h[256:512])
    float* U_s1 = U_s0 + SMEM_U;        // [32][USTRIDE]  (h[0:256])
    float* B_s  = U_s1 + SMEM_U;        // [64]

    const int tid = threadIdx.x;
    const int bx  = blockIdx.x;
    const int gb  = bx & (GB - 1);
    const int gj  = bx >> 2;
    const int b0  = gb * BC;
    const int j0  = gj * JC;

    // ---- one-time: weight tile into SMEM (rows 0-15 r, 16-31 z, 32-47 n) ----
    for (int idx = tid; idx < 48 * 768; idx += NTHR) {
        int row = idx / 768;
        int col = idx - row * 768;
        int G;
        if (row < 16)      G = j0 + row;
        else if (row < 32) G = 512 + j0 + (row - 16);
        else               G = 1024 + j0 + (row - 32);
        float v = (col < II) ? W_ih[G * II + col] : W_hh[G * HH + (col - II)];
        W_s[row * WSTRIDE + col] = v;
    }
    if (tid < 64) {
        int i = tid & 15;
        float v;
        if (tid < 16)      v = b_ih[j0 + i]       + b_hh[j0 + i];        // r
        else if (tid < 32) v = b_ih[512 + j0 + i] + b_hh[512 + j0 + i];  // z
        else if (tid < 48) v = b_ih[1024 + j0 + i];                      // xn
        else               v = b_hh[1024 + j0 + i];                      // hn
        B_s[tid] = v;
    }

    // zero h0, stage x(t=0) into buf0
    for (int idx = bx * NTHR + tid; idx < BATCH * HH; idx += NCTA * NTHR)
        g_h[0][idx] = 0.0f;

    const int ldrow = tid >> 4;          // 0..31
    const int ldv   = tid & 15;          // 0..15
    {
        const float4* xsrc = (const float4*)(x + ((size_t)(b0 + ldrow) * TT) * II);
        float4* dx = (float4*)(U_s0 + ldrow * USTRIDE);
        #pragma unroll
        for (int it = 0; it < 4; it++)
            dx[ldv + 16 * it] = xsrc[ldv + 16 * it];
    }

    grid_sync_full();   // phase -> 1; h0 + x(0) visible

    // thread mapping
    const int s     = tid & 3;           // k-slice lane
    const int bslot = (tid >> 2) & 15;   // batch slots: rows bslot, bslot+16
    const int jp    = tid >> 6;          // 0..7 -> j pair

    const float br_[2]  = { B_s[2*jp],      B_s[2*jp + 1] };
    const float bz_[2]  = { B_s[16 + 2*jp], B_s[16 + 2*jp + 1] };
    const float bxn_[2] = { B_s[32 + 2*jp], B_s[32 + 2*jp + 1] };
    const float bhn_[2] = { B_s[48 + 2*jp], B_s[48 + 2*jp + 1] };

    // W row pointers (ulonglong2 units), k-slice s baked in
    const ulonglong2* wR[2], * wZ[2], * wN[2];
    wR[0] = (const ulonglong2*)(W_s + (2*jp+0)*WSTRIDE) + s;
    wR[1] = (const ulonglong2*)(W_s + (2*jp+1)*WSTRIDE) + s;
    wZ[0] = (const ulonglong2*)(W_s + (16+2*jp+0)*WSTRIDE) + s;
    wZ[1] = (const ulonglong2*)(W_s + (16+2*jp+1)*WSTRIDE) + s;
    wN[0] = (const ulonglong2*)(W_s + (32+2*jp+0)*WSTRIDE) + s;
    wN[1] = (const ulonglong2*)(W_s + (32+2*jp+1)*WSTRIDE) + s;

    const ulonglong2* u0base0 = (const ulonglong2*)(U_s0 + bslot*USTRIDE) + s;
    const ulonglong2* u1base0 = (const ulonglong2*)(U_s0 + (bslot+16)*USTRIDE) + s;
    const ulonglong2* u0base1 = (const ulonglong2*)(U_s1 + bslot*USTRIDE) + s;
    const ulonglong2* u1base1 = (const ulonglong2*)(U_s1 + (bslot+16)*USTRIDE) + s;

    for (int t = 0; t < TT; t++) {
        const int rp = t & 1;
        const int wp = rp ^ 1;

        ull ar[2][2], az[2][2], an[2][2];
        float xn[2][2];
        #pragma unroll
        for (int jj = 0; jj < 2; jj++)
            #pragma unroll
            for (int q = 0; q < 2; q++) { ar[jj][q] = 0; az[jj][q] = 0; an[jj][q] = 0; }

        // ---- chunk 0: x gates from buf0 (no dependence on peers' h) ----
        {
            const ulonglong2* pR0 = wR[0], * pR1 = wR[1];
            const ulonglong2* pZ0 = wZ[0], * pZ1 = wZ[1];
            const ulonglong2* pN0 = wN[0], * pN1 = wN[1];
            const ulonglong2* pu0 = u0base0, * pu1 = u1base0;
            #pragma unroll 4
            for (int i = 0; i < 16; i++) {
                ulonglong2 r0 = pR0[4*i], r1 = pR1[4*i];
                ulonglong2 z0 = pZ0[4*i], z1 = pZ1[4*i];
                ulonglong2 n0 = pN0[4*i], n1 = pN1[4*i];
                ulonglong2 ua = pu0[4*i], ub = pu1[4*i];
                fma2(ar[0][0], r0.x, ua.x); fma2(ar[0][0], r0.y, ua.y);
                fma2(ar[0][1], r0.x, ub.x); fma2(ar[0][1], r0.y, ub.y);
                fma2(ar[1][0], r1.x, ua.x); fma2(ar[1][0], r1.y, ua.y);
                fma2(ar[1][1], r1.x, ub.x); fma2(ar[1][1], r1.y, ub.y);
                fma2(az[0][0], z0.x, ua.x); fma2(az[0][0], z0.y, ua.y);
                fma2(az[0][1], z0.x, ub.x); fma2(az[0][1], z0.y, ub.y);
                fma2(az[1][0], z1.x, ua.x); fma2(az[1][0], z1.y, ua.y);
                fma2(az[1][1], z1.x, ub.x); fma2(az[1][1], z1.y, ub.y);
                fma2(an[0][0], n0.x, ua.x); fma2(an[0][0], n0.y, ua.y);
                fma2(an[0][1], n0.x, ub.x); fma2(an[0][1], n0.y, ub.y);
                fma2(an[1][0], n1.x, ua.x); fma2(an[1][0], n1.y, ua.y);
                fma2(an[1][1], n1.x, ub.x); fma2(an[1][1], n1.y, ub.y);
            }
        }
        #pragma unroll
        for (int jj = 0; jj < 2; jj++)
            #pragma unroll
            for (int q = 0; q < 2; q++) { xn[jj][q] = foldadd(an[jj][q]); an[jj][q] = 0; }

        // ---- wait for peers' h(t-1) (overlapped by chunk-0 compute above) ----
        if (tid == 0) {
            while (*((volatile unsigned*)&g_phase) < (unsigned)(t + 1)) { __nanosleep(32); }
            __threadfence();
        }
        __syncthreads();

        // ---- stage h: h[0:256] -> buf1, h[256:512] -> buf0 ----
        {
            const float4* hsrc = (const float4*)(g_h[rp] + (b0 + ldrow) * HH);
            float4* d1 = (float4*)(U_s1 + ldrow * USTRIDE);
            float4* d0 = (float4*)(U_s0 + ldrow * USTRIDE);
            #pragma unroll
            for (int it = 0; it < 4; it++) d1[ldv + 16*it] = hsrc[ldv + 16*it];
            #pragma unroll
            for (int it = 0; it < 4; it++) d0[ldv + 16*it] = hsrc[64 + ldv + 16*it];
        }
        __syncthreads();

        // ---- chunks 1 (buf1) and 2 (buf0): h gates ----
        #pragma unroll
        for (int c = 1; c < 3; c++) {
            const ulonglong2* pR0 = wR[0] + c*64, * pR1 = wR[1] + c*64;
            const ulonglong2* pZ0 = wZ[0] + c*64, * pZ1 = wZ[1] + c*64;
            const ulonglong2* pN0 = wN[0] + c*64, * pN1 = wN[1] + c*64;
            const ulonglong2* pu0 = (c == 1) ? u0base1 : u0base0;
            const ulonglong2* pu1 = (c == 1) ? u1base1 : u1base0;
            #pragma unroll 4
            for (int i = 0; i < 16; i++) {
                ulonglong2 r0 = pR0[4*i], r1 = pR1[4*i];
                ulonglong2 z0 = pZ0[4*i], z1 = pZ1[4*i];
                ulonglong2 n0 = pN0[4*i], n1 = pN1[4*i];
                ulonglong2 ua = pu0[4*i], ub = pu1[4*i];
                fma2(ar[0][0], r0.x, ua.x); fma2(ar[0][0], r0.y, ua.y);
                fma2(ar[0][1], r0.x, ub.x); fma2(ar[0][1], r0.y, ub.y);
                fma2(ar[1][0], r1.x, ua.x); fma2(ar[1][0], r1.y, ua.y);
                fma2(ar[1][1], r1.x, ub.x); fma2(ar[1][1], r1.y, ub.y);
                fma2(az[0][0], z0.x, ua.x); fma2(az[0][0], z0.y, ua.y);
                fma2(az[0][1], z0.x, ub.x); fma2(az[0][1], z0.y, ub.y);
                fma2(az[1][0], z1.x, ua.x); fma2(az[1][0], z1.y, ua.y);
                fma2(az[1][1], z1.x, ub.x); fma2(az[1][1], z1.y, ub.y);
                fma2(an[0][0], n0.x, ua.x); fma2(an[0][0], n0.y, ua.y);
                fma2(an[0][1], n0.x, ub.x); fma2(an[0][1], n0.y, ub.y);
                fma2(an[1][0], n1.x, ua.x); fma2(an[1][0], n1.y, ua.y);
                fma2(an[1][1], n1.x, ub.x); fma2(an[1][1], n1.y, ub.y);
            }
        }

        // ---- reduce + gates + h update ----
        float vr[2][2], vz[2][2], vh[2][2];
        #pragma unroll
        for (int jj = 0; jj < 2; jj++)
            #pragma unroll
            for (int q = 0; q < 2; q++) {
                vr[jj][q] = red4(foldadd(ar[jj][q]));
                vz[jj][q] = red4(foldadd(az[jj][q]));
                vh[jj][q] = red4(foldadd(an[jj][q]));
                xn[jj][q] = red4(xn[jj][q]);
            }

        if (s == 0) {
            #pragma unroll
            for (int q = 0; q < 2; q++) {
                const int b_local = bslot + 16 * q;
                const int bg = b0 + b_local;
                float2 hnew;
                #pragma unroll
                for (int jj = 0; jj < 2; jj++) {
                    const int j = j0 + 2 * jp + jj;
                    float r = sigm(vr[jj][q] + br_[jj]);
                    float z = sigm(vz[jj][q] + bz_[jj]);
                    float n = tanhf(xn[jj][q] + bxn_[jj] + r * (vh[jj][q] + bhn_[jj]));
                    const float* hbuf = (j < 256) ? U_s1 : U_s0;
                    float hold = hbuf[b_local * USTRIDE + (j & 255)];
                    float hv = n + z * (hold - n);
                    if (jj == 0) hnew.x = hv; else hnew.y = hv;
                }
                *(float2*)(g_h[wp] + bg * HH + j0 + 2 * jp) = hnew;
                if (t == TT - 1)
                    *(float2*)(out + bg * HH + j0 + 2 * jp) = hnew;
            }
        }

        __syncthreads();   // all h writes + all buf0/buf1 reads done

        // ---- arrive (peers may proceed once all CTAs reach here) ----
        if (tid == 0) {
            __threadfence();
            if (atomicAdd(&g_count, 1u) == NCTA - 1u) {
                g_count = 0;
                __threadfence();
                *((volatile unsigned*)&g_phase) = (unsigned)(t + 2);
            }
        }

        // ---- stage x(t+1) into buf0 (independent of peers) ----
        if (t < TT - 1) {
            const float4* xsrc = (const float4*)(x + ((size_t)(b0 + ldrow) * TT + (t + 1)) * II);
            float4* dx = (float4*)(U_s0 + ldrow * USTRIDE);
            #pragma unroll
            for (int it = 0; it < 4; it++)
                dx[ldv + 16 * it] = xsrc[ldv + 16 * it];
        }
        __syncthreads();
    }
}

extern "C" void kernel_launch(void* const* d_in, const int* in_sizes, int n_in,
                              void* d_out, int out_size) {
    (void)in_sizes; (void)n_in; (void)out_size;
    cudaFuncSetAttribute(gru_persistent_kernel,
                         cudaFuncAttributeMaxDynamicSharedMemorySize, SMEM_BYTES);
    gru_persistent_kernel<<<NCTA, NTHR, SMEM_BYTES>>>(
        (const float*)d_in[0],
        (const float*)d_in[1],
        (const float*)d_in[2],
        (const float*)d_in[3],
        (const float*)d_in[4],
        (float*)d_out);
}